// round 13
// baseline (speedup 1.0000x reference)
#include <cuda_runtime.h>

// ManifoldValuedVolterra on S^2 — R4 config, SIMD-FOLD dot association.
//
// Evidence: score depends ONLY on the dot's rounding pattern (all theta
// chains tie to 2e-6); five dot forms tried, none match the reference.
// The one untested 3-term association is the SIMD horizontal-reduce fold:
//   [t0,t1,t2,0] -> [t0+t2, t1] -> (t0+t2)+t1
// which is what XLA's vectorized minor-axis reduce emits. This kernel is
// byte-identical to R4 except:  d = (t0 + t2) + t1  (rn mul/add, no fma).

#define NC   4
#define ND   64
#define NH   64
#define NW_  64
#define NDO  62
#define NTAP 27

__global__ __launch_bounds__(128)
void mvv_kernel(const float* __restrict__ x,
                const float* __restrict__ w1,
                const float* __restrict__ w2,
                const float* __restrict__ w3,
                float* __restrict__ out)
{
    // Packed weights: sw[(o*27+tap)*4 + i] = (w1, w2, w3, 0)
    __shared__ float4 sw[NC * NTAP * NC];

    const int t = threadIdx.y * 32 + threadIdx.x;
    for (int j = t; j < NC * NTAP * NC; j += 128) {
        sw[j] = make_float4(w1[j], w2[j], w3[j], 0.0f);
    }
    __syncthreads();

    const int ox = blockIdx.x * 32 + threadIdx.x;
    const int oy = blockIdx.y * 4 + threadIdx.y;
    // blockIdx.z encodes (b, oz, o): z = (b*NDO + oz)*NC + o
    const int z  = blockIdx.z;
    const int o  = z & 3;
    const int bz = z >> 2;
    const int b  = bz / NDO;
    const int oz = bz - b * NDO;
    if (ox >= NDO || oy >= NDO) return;

    const long planeDHW3 = (long)ND * NH * NW_ * 3;   // channel stride (floats)
    const float* xb = x + (long)b * NC * planeDHW3;

    // Center point p for this output channel
    const float* pp = xb + (long)o * planeDHW3
                    + (((long)(oz + 1) * NH + (oy + 1)) * NW_ + (ox + 1)) * 3;
    const float px = __ldg(pp + 0);
    const float py = __ldg(pp + 1);
    const float pz = __ldg(pp + 2);

    float S[9];
#pragma unroll
    for (int j = 0; j < 9; j++) S[j] = 0.0f;

    const float CLIP_LO = (float)(-1.0 + 1e-6);
    const float CLIP_HI = (float)( 1.0 - 1e-6);

    const int wbase = o * NTAP * NC;

#pragma unroll 1
    for (int kz = 0; kz < 3; kz++) {
#pragma unroll 1
        for (int ky = 0; ky < 3; ky++) {
#pragma unroll 1
            for (int kx = 0; kx < 3; kx++) {
                const int tap = (kz * 3 + ky) * 3 + kx;
                const float* qb = xb + (((long)(oz + kz) * NH + (oy + ky)) * NW_ + (ox + kx)) * 3;

                float ts[9];
#pragma unroll
                for (int j = 0; j < 9; j++) ts[j] = 0.0f;

#pragma unroll
                for (int i = 0; i < NC; i++) {
                    const float* q = qb + (long)i * planeDHW3;
                    const float qx = __ldg(q + 0);
                    const float qy = __ldg(q + 1);
                    const float qz = __ldg(q + 2);

                    // dot SIMD-FOLD: (t0 + t2) + t1   <-- experiment variable
                    float d = __fadd_rn(__fadd_rn(__fmul_rn(px, qx),
                                                  __fmul_rn(pz, qz)),
                                        __fmul_rn(py, qy));
                    d = fminf(fmaxf(d, CLIP_LO), CLIP_HI);

                    // XLA acos lowering: 2*atan2(sqrt(1 - d*d), 1 + d)
                    const float s2 = __fsub_rn(1.0f, __fmul_rn(d, d));
                    const float th = __fmul_rn(2.0f,
                                       atan2f(sqrtf(s2), __fadd_rn(1.0f, d)));
                    const float g  = __fdiv_rn(th, sinf(th));   // theta/sin(theta)

                    // r = q - d*p, no contraction
                    const float rx = __fsub_rn(qx, __fmul_rn(d, px));
                    const float ry = __fsub_rn(qy, __fmul_rn(d, py));
                    const float rz = __fsub_rn(qz, __fmul_rn(d, pz));

                    const float lx = __fmul_rn(g, rx);
                    const float ly = __fmul_rn(g, ry);
                    const float lz = __fmul_rn(g, rz);

                    const float4 wv = sw[wbase + tap * 4 + i];

                    ts[0] = __fadd_rn(ts[0], __fmul_rn(wv.x, lx));
                    ts[1] = __fadd_rn(ts[1], __fmul_rn(wv.x, ly));
                    ts[2] = __fadd_rn(ts[2], __fmul_rn(wv.x, lz));
                    ts[3] = __fadd_rn(ts[3], __fmul_rn(wv.y, lx));
                    ts[4] = __fadd_rn(ts[4], __fmul_rn(wv.y, ly));
                    ts[5] = __fadd_rn(ts[5], __fmul_rn(wv.y, lz));
                    ts[6] = __fadd_rn(ts[6], __fmul_rn(wv.z, lx));
                    ts[7] = __fadd_rn(ts[7], __fmul_rn(wv.z, ly));
                    ts[8] = __fadd_rn(ts[8], __fmul_rn(wv.z, lz));
                }

#pragma unroll
                for (int j = 0; j < 9; j++) S[j] = __fadd_rn(S[j], ts[j]);
            }
        }
    }

    const float l1x = S[0], l1y = S[1], l1z = S[2];
    const float l2x = S[3], l2y = S[4], l2z = S[5];
    const float l3x = S[6], l3y = S[7], l3z = S[8];

    // v = log1 + log2*log3
    const float vx = __fadd_rn(l1x, __fmul_rn(l2x, l3x));
    const float vy = __fadd_rn(l1y, __fmul_rn(l2y, l3y));
    const float vz = __fadd_rn(l1z, __fmul_rn(l2z, l3z));

    // n = sqrt(vx^2 + vy^2 + vz^2 + 1e-12), reference op order
    const float n2 = __fadd_rn(__fadd_rn(__fadd_rn(__fmul_rn(vx, vx),
                                                   __fmul_rn(vy, vy)),
                                         __fmul_rn(vz, vz)), 1e-12f);
    const float n  = sqrtf(n2);
    const float sn = sinf(n);
    const float cn = cosf(n);
    const float k  = __fdiv_rn(sn, n);

    float* op = out + (((((long)b * NC + o) * NDO + oz) * NDO + oy) * NDO + ox) * 3;
    op[0] = __fadd_rn(__fmul_rn(cn, px), __fmul_rn(k, vx));
    op[1] = __fadd_rn(__fmul_rn(cn, py), __fmul_rn(k, vy));
    op[2] = __fadd_rn(__fmul_rn(cn, pz), __fmul_rn(k, vz));
}

extern "C" void kernel_launch(void* const* d_in, const int* in_sizes, int n_in,
                              void* d_out, int out_size)
{
    const float* x  = (const float*)d_in[0];
    const float* w1 = (const float*)d_in[1];
    const float* w2 = (const float*)d_in[2];
    const float* w3 = (const float*)d_in[3];
    float* out = (float*)d_out;

    dim3 blk(32, 4, 1);
    dim3 grd((NDO + 31) / 32, (NDO + 3) / 4, 2 * NDO * NC);  // (2, 16, 496)
    mvv_kernel<<<grd, blk>>>(x, w1, w2, w3, out);
}

// round 14
// speedup vs baseline: 1.9358x; 1.9358x over previous
#include <cuda_runtime.h>

// ManifoldValuedVolterra on S^2 — passing config (SIMD-fold dot) + fast g.
//
// LOCKED numerics (do not touch): dot = rn((t0 + t2) + t1)  [SIMD fold,
// matches the reference's vectorized reduce], clip to +/-(1 - 1e-6).
// The theta-chain implementation only affects score at ~2e-6, so we use the
// cheap accurate form:
//   g = acosf(d) * rsqrtf(fma(-d, d, 1))     (~15 issue slots vs ~60 for
//   atan2f + sinf + IEEE div; per-term rel error ~5e-7, 30x inside budget)
// Einsum / tap accumulation unchanged (rn mul/add, i ascending, tap order).

#define NC   4
#define ND   64
#define NH   64
#define NW_  64
#define NDO  62
#define NTAP 27

__global__ __launch_bounds__(128)
void mvv_kernel(const float* __restrict__ x,
                const float* __restrict__ w1,
                const float* __restrict__ w2,
                const float* __restrict__ w3,
                float* __restrict__ out)
{
    // Packed weights: sw[(o*27+tap)*4 + i] = (w1, w2, w3, 0)
    __shared__ float4 sw[NC * NTAP * NC];

    const int t = threadIdx.y * 32 + threadIdx.x;
    for (int j = t; j < NC * NTAP * NC; j += 128) {
        sw[j] = make_float4(w1[j], w2[j], w3[j], 0.0f);
    }
    __syncthreads();

    const int ox = blockIdx.x * 32 + threadIdx.x;
    const int oy = blockIdx.y * 4 + threadIdx.y;
    // blockIdx.z encodes (b, oz, o): z = (b*NDO + oz)*NC + o
    const int z  = blockIdx.z;
    const int o  = z & 3;
    const int bz = z >> 2;
    const int b  = bz / NDO;
    const int oz = bz - b * NDO;
    if (ox >= NDO || oy >= NDO) return;

    const int plane = ND * NH * NW_ * 3;              // channel stride (floats)
    const float* xb = x + (long)b * NC * plane;       // batch base

    // Center point p for this output channel (32-bit offsets inside batch)
    const int pOff = o * plane + (((oz + 1) * NH + (oy + 1)) * NW_ + (ox + 1)) * 3;
    const float px = __ldg(xb + pOff + 0);
    const float py = __ldg(xb + pOff + 1);
    const float pz = __ldg(xb + pOff + 2);

    float S[9];
#pragma unroll
    for (int j = 0; j < 9; j++) S[j] = 0.0f;

    const float CLIP_LO = (float)(-1.0 + 1e-6);
    const float CLIP_HI = (float)( 1.0 - 1e-6);

    const int wbase = o * NTAP * NC;
    const int vox0  = ((oz * NH + oy) * NW_ + ox) * 3;   // tap (0,0,0) corner

#pragma unroll 1
    for (int kz = 0; kz < 3; kz++) {
#pragma unroll 1
        for (int ky = 0; ky < 3; ky++) {
            const int rowOff = vox0 + ((kz * NH + ky) * NW_) * 3;
            const int tapRow = (kz * 3 + ky) * 3;
#pragma unroll
            for (int kx = 0; kx < 3; kx++) {
                const int tap  = tapRow + kx;
                const int qOff = rowOff + kx * 3;

                float ts[9];
#pragma unroll
                for (int j = 0; j < 9; j++) ts[j] = 0.0f;

#pragma unroll
                for (int i = 0; i < NC; i++) {
                    const float* q = xb + qOff + i * plane;
                    const float qx = __ldg(q + 0);
                    const float qy = __ldg(q + 1);
                    const float qz = __ldg(q + 2);

                    // dot SIMD-FOLD (LOCKED): (t0 + t2) + t1, rn, no fma
                    float d = __fadd_rn(__fadd_rn(__fmul_rn(px, qx),
                                                  __fmul_rn(pz, qz)),
                                        __fmul_rn(py, qy));
                    d = fminf(fmaxf(d, CLIP_LO), CLIP_HI);

                    // Fast accurate g = acos(d)/sin(acos(d))
                    const float s2 = fmaf(-d, d, 1.0f);   // exact near pole
                    const float g  = acosf(d) * rsqrtf(s2);

                    // lg = g * (q - d*p)
                    const float lx = g * __fsub_rn(qx, __fmul_rn(d, px));
                    const float ly = g * __fsub_rn(qy, __fmul_rn(d, py));
                    const float lz = g * __fsub_rn(qz, __fmul_rn(d, pz));

                    const float4 wv = sw[wbase + tap * 4 + i];

                    ts[0] = __fadd_rn(ts[0], __fmul_rn(wv.x, lx));
                    ts[1] = __fadd_rn(ts[1], __fmul_rn(wv.x, ly));
                    ts[2] = __fadd_rn(ts[2], __fmul_rn(wv.x, lz));
                    ts[3] = __fadd_rn(ts[3], __fmul_rn(wv.y, lx));
                    ts[4] = __fadd_rn(ts[4], __fmul_rn(wv.y, ly));
                    ts[5] = __fadd_rn(ts[5], __fmul_rn(wv.y, lz));
                    ts[6] = __fadd_rn(ts[6], __fmul_rn(wv.z, lx));
                    ts[7] = __fadd_rn(ts[7], __fmul_rn(wv.z, ly));
                    ts[8] = __fadd_rn(ts[8], __fmul_rn(wv.z, lz));
                }

#pragma unroll
                for (int j = 0; j < 9; j++) S[j] = __fadd_rn(S[j], ts[j]);
            }
        }
    }

    const float l1x = S[0], l1y = S[1], l1z = S[2];
    const float l2x = S[3], l2y = S[4], l2z = S[5];
    const float l3x = S[6], l3y = S[7], l3z = S[8];

    // v = log1 + log2*log3
    const float vx = __fadd_rn(l1x, __fmul_rn(l2x, l3x));
    const float vy = __fadd_rn(l1y, __fmul_rn(l2y, l3y));
    const float vz = __fadd_rn(l1z, __fmul_rn(l2z, l3z));

    // n = sqrt(|v|^2 + 1e-12)
    const float n2 = __fadd_rn(__fadd_rn(__fadd_rn(__fmul_rn(vx, vx),
                                                   __fmul_rn(vy, vy)),
                                         __fmul_rn(vz, vz)), 1e-12f);
    const float n  = sqrtf(n2);
    float sn, cn;
    sincosf(n, &sn, &cn);
    const float k = __fdiv_rn(sn, n);

    float* op = out + (((((long)b * NC + o) * NDO + oz) * NDO + oy) * NDO + ox) * 3;
    op[0] = __fadd_rn(__fmul_rn(cn, px), __fmul_rn(k, vx));
    op[1] = __fadd_rn(__fmul_rn(cn, py), __fmul_rn(k, vy));
    op[2] = __fadd_rn(__fmul_rn(cn, pz), __fmul_rn(k, vz));
}

extern "C" void kernel_launch(void* const* d_in, const int* in_sizes, int n_in,
                              void* d_out, int out_size)
{
    const float* x  = (const float*)d_in[0];
    const float* w1 = (const float*)d_in[1];
    const float* w2 = (const float*)d_in[2];
    const float* w3 = (const float*)d_in[3];
    float* out = (float*)d_out;

    dim3 blk(32, 4, 1);
    dim3 grd((NDO + 31) / 32, (NDO + 3) / 4, 2 * NDO * NC);  // (2, 16, 496)
    mvv_kernel<<<grd, blk>>>(x, w1, w2, w3, out);
}

// round 15
// speedup vs baseline: 2.3472x; 1.2125x over previous
#include <cuda_runtime.h>

// ManifoldValuedVolterra on S^2 — issue-slot diet round.
//
// LOCKED numerics (the only score-critical bits): dot = rn((t0+t2)+t1)
// [SIMD fold matching the reference's vectorized reduce], clip +/-(1-1e-6),
// s2 = fma(-d,d,1) (exact near pole), g = acosf(d)*rsqrtf(s2).
// Downstream rounding is unamplified (established R2/R7/R9 nulls), so:
//   - r via fmaf(-d, p, q)              (3 slots, was 6)
//   - einsum via fmaf into S directly   (9 slots, was 18 + 4.5 staging)
// Error budget: adds ~4e-5 unamplified noise; rel_err stays ~5e-5 << 1e-3.

#define NC   4
#define ND   64
#define NH   64
#define NW_  64
#define NDO  62
#define NTAP 27

__global__ __launch_bounds__(128)
void mvv_kernel(const float* __restrict__ x,
                const float* __restrict__ w1,
                const float* __restrict__ w2,
                const float* __restrict__ w3,
                float* __restrict__ out)
{
    // Packed weights: sw[(o*27+tap)*4 + i] = (w1, w2, w3, 0)
    __shared__ float4 sw[NC * NTAP * NC];

    const int t = threadIdx.y * 32 + threadIdx.x;
    for (int j = t; j < NC * NTAP * NC; j += 128) {
        sw[j] = make_float4(w1[j], w2[j], w3[j], 0.0f);
    }
    __syncthreads();

    const int ox = blockIdx.x * 32 + threadIdx.x;
    const int oy = blockIdx.y * 4 + threadIdx.y;
    // blockIdx.z encodes (b, oz, o): z = (b*NDO + oz)*NC + o
    const int z  = blockIdx.z;
    const int o  = z & 3;
    const int bz = z >> 2;
    const int b  = bz / NDO;
    const int oz = bz - b * NDO;
    if (ox >= NDO || oy >= NDO) return;

    const int plane = ND * NH * NW_ * 3;              // channel stride (floats)
    const float* xb = x + (long)b * NC * plane;       // batch base

    // Center point p for this output channel
    const int pOff = o * plane + (((oz + 1) * NH + (oy + 1)) * NW_ + (ox + 1)) * 3;
    const float px = __ldg(xb + pOff + 0);
    const float py = __ldg(xb + pOff + 1);
    const float pz = __ldg(xb + pOff + 2);

    float S[9];
#pragma unroll
    for (int j = 0; j < 9; j++) S[j] = 0.0f;

    const float CLIP_LO = (float)(-1.0 + 1e-6);
    const float CLIP_HI = (float)( 1.0 - 1e-6);

    const int wbase = o * NTAP * NC;
    const int vox0  = ((oz * NH + oy) * NW_ + ox) * 3;   // tap (0,0,0) corner

#pragma unroll 1
    for (int kz = 0; kz < 3; kz++) {
#pragma unroll 1
        for (int ky = 0; ky < 3; ky++) {
            const int rowOff = vox0 + ((kz * NH + ky) * NW_) * 3;
            const int tapRow = (kz * 3 + ky) * 3;
#pragma unroll
            for (int kx = 0; kx < 3; kx++) {
                const int tap  = tapRow + kx;
                const int qOff = rowOff + kx * 3;

#pragma unroll
                for (int i = 0; i < NC; i++) {
                    const float* q = xb + qOff + i * plane;
                    const float qx = __ldg(q + 0);
                    const float qy = __ldg(q + 1);
                    const float qz = __ldg(q + 2);

                    // dot SIMD-FOLD (LOCKED): (t0 + t2) + t1, rn, no fma
                    float d = __fadd_rn(__fadd_rn(__fmul_rn(px, qx),
                                                  __fmul_rn(pz, qz)),
                                        __fmul_rn(py, qy));
                    d = fminf(fmaxf(d, CLIP_LO), CLIP_HI);

                    // g = acos(d)/sin(acos(d)) — fast accurate form
                    const float s2 = fmaf(-d, d, 1.0f);   // exact near pole
                    const float g  = acosf(d) * rsqrtf(s2);

                    // lg = g * (q - d*p), contracted
                    const float lx = g * fmaf(-d, px, qx);
                    const float ly = g * fmaf(-d, py, qy);
                    const float lz = g * fmaf(-d, pz, qz);

                    const float4 wv = sw[wbase + tap * 4 + i];

                    // einsum: straight FMA accumulation into S
                    S[0] = fmaf(wv.x, lx, S[0]);
                    S[1] = fmaf(wv.x, ly, S[1]);
                    S[2] = fmaf(wv.x, lz, S[2]);
                    S[3] = fmaf(wv.y, lx, S[3]);
                    S[4] = fmaf(wv.y, ly, S[4]);
                    S[5] = fmaf(wv.y, lz, S[5]);
                    S[6] = fmaf(wv.z, lx, S[6]);
                    S[7] = fmaf(wv.z, ly, S[7]);
                    S[8] = fmaf(wv.z, lz, S[8]);
                }
            }
        }
    }

    const float l1x = S[0], l1y = S[1], l1z = S[2];
    const float l2x = S[3], l2y = S[4], l2z = S[5];
    const float l3x = S[6], l3y = S[7], l3z = S[8];

    // v = log1 + log2*log3
    const float vx = fmaf(l2x, l3x, l1x);
    const float vy = fmaf(l2y, l3y, l1y);
    const float vz = fmaf(l2z, l3z, l1z);

    // n = sqrt(|v|^2 + 1e-12)
    const float n2 = __fadd_rn(fmaf(vz, vz, fmaf(vy, vy, __fmul_rn(vx, vx))),
                               1e-12f);
    const float n  = sqrtf(n2);
    float sn, cn;
    sincosf(n, &sn, &cn);
    const float k = __fdiv_rn(sn, n);

    float* op = out + (((((long)b * NC + o) * NDO + oz) * NDO + oy) * NDO + ox) * 3;
    op[0] = fmaf(cn, px, __fmul_rn(k, vx));
    op[1] = fmaf(cn, py, __fmul_rn(k, vy));
    op[2] = fmaf(cn, pz, __fmul_rn(k, vz));
}

extern "C" void kernel_launch(void* const* d_in, const int* in_sizes, int n_in,
                              void* d_out, int out_size)
{
    const float* x  = (const float*)d_in[0];
    const float* w1 = (const float*)d_in[1];
    const float* w2 = (const float*)d_in[2];
    const float* w3 = (const float*)d_in[3];
    float* out = (float*)d_out;

    dim3 blk(32, 4, 1);
    dim3 grd((NDO + 31) / 32, (NDO + 3) / 4, 2 * NDO * NC);  // (2, 16, 496)
    mvv_kernel<<<grd, blk>>>(x, w1, w2, w3, out);
}